// round 7
// baseline (speedup 1.0000x reference)
#include <cuda_runtime.h>
#include <math.h>

// ---------------------------------------------------------------------------
// GemoLoss — GB300. n=4, h=768, w=1024, S=131072.
// R6: single-pass decoupled-lookback mask/scan/scatter + deduped gathers.
// ---------------------------------------------------------------------------

#define NIMG 4
#define H    768
#define W    1024
#define P    (H * W)          // 786432
#define S    131072
#define NB   (P / 1024)       // 768 blocks of 1024 pixels per image

#define MASK_VALUE (-1e-8f)

// decoupled-lookback flag encoding (value <= P < 2^30)
#define STATE_AGG 0x40000000u
#define STATE_PFX 0x80000000u
#define VAL_MASK  0x3FFFFFFFu

// -------------------- device scratch (no allocations allowed) ---------------
__device__ float    g_edge [NIMG * P];
__device__ float    g_theta[NIMG * P];
__device__ int      g_esel [NIMG * P];   // stable select array for edge mask
__device__ int      g_vsel [NIMG * P];   // stable select array for valid mask
__device__ unsigned g_emax_bits[NIMG];   // edge max as float bits (edge >= 0)
__device__ unsigned g_eflag[NIMG * NB];  // lookback flags (reset in k_sobel)
__device__ unsigned g_vflag[NIMG * NB];
__device__ int      g_ecount[NIMG];
__device__ int      g_vcount[NIMG];
__device__ double   g_acc_eq;
__device__ double   g_acc_uq;

// ----------------------------------------------------------------------------
__global__ void k_init() {
    int t = threadIdx.x;
    if (t < NIMG) g_emax_bits[t] = 0u;
    if (t == 0) { g_acc_eq = 0.0; g_acc_uq = 0.0; }
}

// ----------------------------------------------------------------------------
// Sobel on channel 0 of images (n,3,h,w). Cross-correlation (lax.conv does not
// flip kernels). Border pixels get edge=0, theta=0. Fused per-image max.
// Also resets the lookback flags for the mask kernel that follows.
__global__ void k_sobel(const float* __restrict__ images) {
    int gid = blockIdx.x * blockDim.x + threadIdx.x;   // < NIMG*P
    if (gid < NIMG * NB) { g_eflag[gid] = 0u; g_vflag[gid] = 0u; }

    int img = gid / P;
    int p   = gid - img * P;
    int y = p / W;
    int x = p - y * W;

    float e = 0.0f, th = 0.0f;
    if (y > 0 && y < H - 1 && x > 0 && x < W - 1) {
        const float* I = images + (size_t)img * 3 * P;
        float a  = __ldg(I + (y - 1) * W + (x - 1));
        float b  = __ldg(I + (y - 1) * W + (x    ));
        float c  = __ldg(I + (y - 1) * W + (x + 1));
        float d  = __ldg(I + (y    ) * W + (x - 1));
        float f  = __ldg(I + (y    ) * W + (x + 1));
        float g  = __ldg(I + (y + 1) * W + (x - 1));
        float hh = __ldg(I + (y + 1) * W + (x    ));
        float i  = __ldg(I + (y + 1) * W + (x + 1));

        // kx = [[-1,0,1],[-2,0,2],[-1,0,1]], ky = [[1,2,1],[0,0,0],[-1,-2,-1]]
        float gx = -a;  gx += c;  gx += -2.0f * d;  gx += 2.0f * f;  gx += -g;  gx += i;
        float gy =  a;  gy += 2.0f * b;  gy += c;  gy += -g;  gy += -2.0f * hh; gy += -i;

        e  = sqrtf(gx * gx + gy * gy);
        th = atan2f(gy, gx);
    }
    g_edge [gid] = e;
    g_theta[gid] = th;

    // block max -> atomicMax (uint order == float order for non-negative)
    __shared__ float smax[8];                 // 256 threads = 8 warps
    int lane = threadIdx.x & 31, wid = threadIdx.x >> 5;
    float m = e;
    #pragma unroll
    for (int off = 16; off; off >>= 1)
        m = fmaxf(m, __shfl_down_sync(0xffffffffu, m, off));
    if (lane == 0) smax[wid] = m;
    __syncthreads();
    if (wid == 0) {
        m = (lane < 8) ? smax[lane] : 0.0f;
        #pragma unroll
        for (int off = 4; off; off >>= 1)
            m = fmaxf(m, __shfl_down_sync(0xffffffffu, m, off));
        if (lane == 0) atomicMax(&g_emax_bits[img], __float_as_uint(m));
    }
}

// ----------------------------------------------------------------------------
// Single-pass mask + scan + stable scatter via decoupled lookback.
// One lookback chain per (image, mask): e on thread 0, v on thread 32.
// Stability: block offsets come from a strictly ordered scan, intra-block
// prefixes preserve pixel order -> identical to argsort(!mask) prefix.
__global__ void k_mask(const float* __restrict__ tgt) {
    int img = blockIdx.x / NB;
    int b   = blockIdx.x - img * NB;
    int tid = threadIdx.x;
    int p   = b * 1024 + tid;

    float thresh = 0.1f * __uint_as_float(g_emax_bits[img]);
    int e = (g_edge[(size_t)img * P + p] >= thresh) ? 1 : 0;
    int v = (__ldg(tgt + (size_t)img * P + p) > MASK_VALUE) ? 1 : 0;

    __shared__ int wse[32], wsv[32];
    __shared__ int s_excl_e, s_excl_v;

    const unsigned full = 0xffffffffu;
    unsigned bal_e = __ballot_sync(full, e != 0);
    unsigned bal_v = __ballot_sync(full, v != 0);
    int lane = tid & 31, wid = tid >> 5;
    unsigned ltmask = (1u << lane) - 1u;
    int lpre_e = __popc(bal_e & ltmask);
    int lpre_v = __popc(bal_v & ltmask);
    if (lane == 0) { wse[wid] = __popc(bal_e); wsv[wid] = __popc(bal_v); }
    __syncthreads();
    if (wid == 0) {                           // scan 32 warp sums (both masks)
        int a = wse[lane], c = wsv[lane];
        #pragma unroll
        for (int off = 1; off < 32; off <<= 1) {
            int ta = __shfl_up_sync(full, a, off);
            int tc = __shfl_up_sync(full, c, off);
            if (lane >= off) { a += ta; c += tc; }
        }
        wse[lane] = a; wsv[lane] = c;         // inclusive
    }
    __syncthreads();
    int base_e = wid ? wse[wid - 1] : 0;
    int base_v = wid ? wsv[wid - 1] : 0;
    int tot_e  = wse[31];
    int tot_v  = wsv[31];

    if (tid == 0) {                           // e-chain lookback
        int excl = 0;
        if (b == 0) {
            atomicExch(&g_eflag[blockIdx.x], STATE_PFX | (unsigned)tot_e);
        } else {
            atomicExch(&g_eflag[blockIdx.x], STATE_AGG | (unsigned)tot_e);
            int i = blockIdx.x - 1;
            while (true) {
                unsigned f = *((volatile unsigned*)&g_eflag[i]);
                if (f & STATE_PFX)      { excl += (int)(f & VAL_MASK); break; }
                else if (f & STATE_AGG) { excl += (int)(f & VAL_MASK); --i; }
                else                    __nanosleep(20);
            }
            atomicExch(&g_eflag[blockIdx.x], STATE_PFX | (unsigned)(excl + tot_e));
        }
        s_excl_e = excl;
        if (b == NB - 1) g_ecount[img] = excl + tot_e;
    }
    if (tid == 32) {                          // v-chain lookback (parallel warp)
        int excl = 0;
        if (b == 0) {
            atomicExch(&g_vflag[blockIdx.x], STATE_PFX | (unsigned)tot_v);
        } else {
            atomicExch(&g_vflag[blockIdx.x], STATE_AGG | (unsigned)tot_v);
            int i = blockIdx.x - 1;
            while (true) {
                unsigned f = *((volatile unsigned*)&g_vflag[i]);
                if (f & STATE_PFX)      { excl += (int)(f & VAL_MASK); break; }
                else if (f & STATE_AGG) { excl += (int)(f & VAL_MASK); --i; }
                else                    __nanosleep(20);
            }
            atomicExch(&g_vflag[blockIdx.x], STATE_PFX | (unsigned)(excl + tot_v));
        }
        s_excl_v = excl;
        if (b == NB - 1) g_vcount[img] = excl + tot_v;
    }
    __syncthreads();

    if (e) g_esel[(size_t)img * P + s_excl_e + base_e + lpre_e] = p;
    if (v) g_vsel[(size_t)img * P + s_excl_v + base_v + lpre_v] = p;
}

// ----------------------------------------------------------------------------
// Main sampling kernel: one thread per (img, s). 4 pairs over 6 distinct
// pixels -> 12 gathers (was 16). All gathers issued before any pair math.
__global__ void k_sample(const float* __restrict__ inp,
                         const float* __restrict__ tgt,
                         const int*   __restrict__ ra,
                         const int*   __restrict__ rd,
                         const int*   __restrict__ rp) {
    int gid = blockIdx.x * blockDim.x + threadIdx.x;
    double eq = 0.0, uq = 0.0;

    if (gid < NIMG * S) {
        int img = gid / S;
        int s   = gid - img * S;
        const float* in_i = inp + (size_t)img * P;
        const float* tg_i = tgt + (size_t)img * P;

        int ec = g_ecount[img];
        int vc = g_vcount[img];

        // anchor = edge_idx[ra % minlen]; empty mask -> identity argsort -> 0
        int anchor = (ec > 0) ? g_esel[(size_t)img * P + (ra[gid] % ec)] : 0;

        float th = g_theta[(size_t)img * P + anchor];
        float ct, st;
        sincosf(th, &st, &ct);
        int row_a = anchor / W;
        int col_a = anchor - row_a * W;

        int q[6];
        #pragma unroll
        for (int j = 0; j < 4; j++) {
            int   rdv  = __ldg(rd + ((size_t)img * 4 + j) * S + s);
            float sign = (j < 2) ? -1.0f : 1.0f;
            float d    = ((float)rdv + 2.0f) * sign;
            int cc = col_a + (int)rintf(d * ct);   // jnp.round = half-to-even
            int rr = row_a + (int)rintf(d * st);
            cc = min(max(cc, 0), W - 1);
            rr = min(max(rr, 0), H - 1);
            q[j] = rr * W + cc;
        }

        if (vc > 0) {
            int2 rpv = __ldg((const int2*)(rp + (size_t)img * 2 * S) + s);
            q[4] = g_vsel[(size_t)img * P + (rpv.x % vc)];
            q[5] = g_vsel[(size_t)img * P + (rpv.y % vc)];
        } else {
            q[4] = 0; q[5] = 0;    // vidx -> identity, rp % 1 = 0
        }

        // issue all 12 gathers up front (max MLP)
        float iv[6], tv[6];
        #pragma unroll
        for (int j = 0; j < 6; j++) iv[j] = __ldg(in_i + q[j]);
        #pragma unroll
        for (int j = 0; j < 6; j++) tv[j] = __ldg(tg_i + q[j]);

        const int PA[4] = {0, 1, 2, 4};
        const int PB[4] = {1, 2, 3, 5};
        const float hi = 1.0f + 0.03f;             // 1 + SIGMA in f32
        const float lo = (float)(1.0 / 1.03);      // double-computed like Python

        #pragma unroll
        for (int k = 0; k < 4; k++) {
            float iA = iv[PA[k]], iB = iv[PB[k]];
            float tA = tv[PA[k]], tB = tv[PB[k]];

            float cm = ((tA > MASK_VALUE) && (tB > MASK_VALUE)) ? 1.0f : 0.0f;
            float ratio = (tA + 1e-6f) / (tB + 1e-6f);
            bool  meq = (ratio < hi) && (ratio > lo);

            if (meq) {
                float dd = iA - iB;
                eq += (double)(dd * dd * cm);
            } else {
                float lbl = (ratio >= hi) ? 1.0f : -1.0f;
                uq += (double)(log1pf(expf((iB - iA) * lbl)) * cm);
            }
        }
    }

    // block reduce (doubles) -> single atomicAdd pair per block
    #pragma unroll
    for (int off = 16; off; off >>= 1) {
        eq += __shfl_down_sync(0xffffffffu, eq, off);
        uq += __shfl_down_sync(0xffffffffu, uq, off);
    }
    __shared__ double sh_eq[8];
    __shared__ double sh_uq[8];
    int lane = threadIdx.x & 31, wid = threadIdx.x >> 5;
    if (lane == 0) { sh_eq[wid] = eq; sh_uq[wid] = uq; }
    __syncthreads();
    if (wid == 0) {
        eq = (lane < 8) ? sh_eq[lane] : 0.0;
        uq = (lane < 8) ? sh_uq[lane] : 0.0;
        #pragma unroll
        for (int off = 4; off; off >>= 1) {
            eq += __shfl_down_sync(0xffffffffu, eq, off);
            uq += __shfl_down_sync(0xffffffffu, uq, off);
        }
        if (lane == 0) {
            atomicAdd(&g_acc_eq, eq);
            atomicAdd(&g_acc_uq, uq);
        }
    }
}

// ----------------------------------------------------------------------------
__global__ void k_final(float* __restrict__ out) {
    const double ALPHA = 1.0;
    double denom = 4.0 * (double)S;                       // pairs per image
    double loss  = (ALPHA * g_acc_eq + g_acc_uq) / denom / (double)NIMG;
    out[0] = (float)loss;
}

// ----------------------------------------------------------------------------
extern "C" void kernel_launch(void* const* d_in, const int* in_sizes, int n_in,
                              void* d_out, int out_size) {
    (void)in_sizes; (void)n_in; (void)out_size;

    const float* inputs  = (const float*)d_in[0];
    const float* targets = (const float*)d_in[1];
    const float* images  = (const float*)d_in[2];
    const int*   ra      = (const int*)d_in[3];
    const int*   rd      = (const int*)d_in[4];
    const int*   rp      = (const int*)d_in[5];
    float*       out     = (float*)d_out;

    k_init  <<<1, 32>>>();
    k_sobel <<<(NIMG * P) / 256, 256>>>(images);
    k_mask  <<<NIMG * NB, 1024>>>(targets);
    k_sample<<<(NIMG * S + 255) / 256, 256>>>(inputs, targets, ra, rd, rp);
    k_final <<<1, 1>>>(out);
}

// round 8
// speedup vs baseline: 1.4162x; 1.4162x over previous
#include <cuda_runtime.h>
#include <math.h>

// ---------------------------------------------------------------------------
// GemoLoss — GB300. n=4, h=768, w=1024, S=131072.
// R7: revert lookback; float2 (inp,tgt) packing; int2 (pixel,theta) packing;
//     scan-free scatter (inline block-offset reduction); float4 mask passes.
// ---------------------------------------------------------------------------

#define NIMG 4
#define H    768
#define W    1024
#define P    (H * W)          // 786432
#define S    131072
#define NB   (P / 1024)       // 768 tiles of 1024 pixels per image

#define MASK_VALUE (-1e-8f)

// -------------------- device scratch (no allocations allowed) ---------------
__device__ float    g_edge [NIMG * P];
__device__ float    g_theta[NIMG * P];
__device__ float2   g_pt   [NIMG * P];   // packed (inp, tgt) per pixel
__device__ int2     g_epack[NIMG * P];   // packed (pixel, theta_bits), edge-selected
__device__ int      g_vsel [NIMG * P];   // stable select array for valid mask
__device__ unsigned g_emax_bits[NIMG];   // edge max as float bits (edge >= 0)
__device__ int      g_eblk[NIMG * NB];   // per-tile mask counts
__device__ int      g_vblk[NIMG * NB];
__device__ int      g_ecount[NIMG];
__device__ int      g_vcount[NIMG];
__device__ double   g_acc_eq;
__device__ double   g_acc_uq;

// ----------------------------------------------------------------------------
__global__ void k_init() {
    int t = threadIdx.x;
    if (t < NIMG) g_emax_bits[t] = 0u;
    if (t == 0) { g_acc_eq = 0.0; g_acc_uq = 0.0; }
}

// ----------------------------------------------------------------------------
// Sobel on channel 0 of images (n,3,h,w), cross-correlation (lax.conv does not
// flip kernels). Border pixels get edge=0, theta=0. Fused per-image max.
// Also packs (inp,tgt) into g_pt for sector-efficient gathers in k_sample.
__global__ void k_sobel(const float* __restrict__ images,
                        const float* __restrict__ inp,
                        const float* __restrict__ tgt) {
    int gid = blockIdx.x * blockDim.x + threadIdx.x;   // < NIMG*P
    int img = gid / P;
    int p   = gid - img * P;
    int y = p / W;
    int x = p - y * W;

    g_pt[gid] = make_float2(__ldg(inp + gid), __ldg(tgt + gid));

    float e = 0.0f, th = 0.0f;
    if (y > 0 && y < H - 1 && x > 0 && x < W - 1) {
        const float* I = images + (size_t)img * 3 * P;
        float a  = __ldg(I + (y - 1) * W + (x - 1));
        float b  = __ldg(I + (y - 1) * W + (x    ));
        float c  = __ldg(I + (y - 1) * W + (x + 1));
        float d  = __ldg(I + (y    ) * W + (x - 1));
        float f  = __ldg(I + (y    ) * W + (x + 1));
        float g  = __ldg(I + (y + 1) * W + (x - 1));
        float hh = __ldg(I + (y + 1) * W + (x    ));
        float i  = __ldg(I + (y + 1) * W + (x + 1));

        // kx = [[-1,0,1],[-2,0,2],[-1,0,1]], ky = [[1,2,1],[0,0,0],[-1,-2,-1]]
        float gx = -a;  gx += c;  gx += -2.0f * d;  gx += 2.0f * f;  gx += -g;  gx += i;
        float gy =  a;  gy += 2.0f * b;  gy += c;  gy += -g;  gy += -2.0f * hh; gy += -i;

        e  = sqrtf(gx * gx + gy * gy);
        th = atan2f(gy, gx);
    }
    g_edge [gid] = e;
    g_theta[gid] = th;

    // block max -> atomicMax (uint order == float order for non-negative)
    __shared__ float smax[8];                 // 256 threads = 8 warps
    int lane = threadIdx.x & 31, wid = threadIdx.x >> 5;
    float m = e;
    #pragma unroll
    for (int off = 16; off; off >>= 1)
        m = fmaxf(m, __shfl_down_sync(0xffffffffu, m, off));
    if (lane == 0) smax[wid] = m;
    __syncthreads();
    if (wid == 0) {
        m = (lane < 8) ? smax[lane] : 0.0f;
        #pragma unroll
        for (int off = 4; off; off >>= 1)
            m = fmaxf(m, __shfl_down_sync(0xffffffffu, m, off));
        if (lane == 0) atomicMax(&g_emax_bits[img], __float_as_uint(m));
    }
}

// ----------------------------------------------------------------------------
// Per-tile (1024 px) mask counts. 256 threads, 4 px/thread via float4.
__global__ void k_count(const float* __restrict__ tgt) {
    int img = blockIdx.x / NB;
    int b   = blockIdx.x - img * NB;
    int tid = threadIdx.x;
    size_t base = (size_t)img * P + (size_t)b * 1024;

    float thresh = 0.1f * __uint_as_float(g_emax_bits[img]);
    float4 ed = *(const float4*)(g_edge + base + tid * 4);
    float4 tg = __ldg((const float4*)(tgt + base) + tid);

    int ce = (ed.x >= thresh) + (ed.y >= thresh) + (ed.z >= thresh) + (ed.w >= thresh);
    int cv = (tg.x > MASK_VALUE) + (tg.y > MASK_VALUE) + (tg.z > MASK_VALUE) + (tg.w > MASK_VALUE);

    __shared__ int sce[8], scv[8];
    int lane = tid & 31, wid = tid >> 5;
    #pragma unroll
    for (int off = 16; off; off >>= 1) {
        ce += __shfl_down_sync(0xffffffffu, ce, off);
        cv += __shfl_down_sync(0xffffffffu, cv, off);
    }
    if (lane == 0) { sce[wid] = ce; scv[wid] = cv; }
    __syncthreads();
    if (tid == 0) {
        int te = 0, tv = 0;
        #pragma unroll
        for (int i = 0; i < 8; i++) { te += sce[i]; tv += scv[i]; }
        g_eblk[img * NB + b] = te;
        g_vblk[img * NB + b] = tv;
    }
}

// ----------------------------------------------------------------------------
// Stable scatter. 256 threads, 4 consecutive px/thread (preserves pixel order).
// Tile offset = sum of preceding tile counts, reduced inline (no scan kernel).
// Writes g_epack = (pixel, theta_bits) and g_vsel = pixel.
__global__ void k_scatter(const float* __restrict__ tgt) {
    int img = blockIdx.x / NB;
    int b   = blockIdx.x - img * NB;
    int tid = threadIdx.x;
    int lane = tid & 31, wid = tid >> 5;
    size_t base = (size_t)img * P + (size_t)b * 1024;

    float thresh = 0.1f * __uint_as_float(g_emax_bits[img]);
    float4 ed = *(const float4*)(g_edge + base + tid * 4);
    float4 tg = __ldg((const float4*)(tgt + base) + tid);
    float4 th = *(const float4*)(g_theta + base + tid * 4);

    int e[4] = { ed.x >= thresh, ed.y >= thresh, ed.z >= thresh, ed.w >= thresh };
    int v[4] = { tg.x > MASK_VALUE, tg.y > MASK_VALUE, tg.z > MASK_VALUE, tg.w > MASK_VALUE };
    float thv[4] = { th.x, th.y, th.z, th.w };

    int ce = e[0] + e[1] + e[2] + e[3];
    int cv = v[0] + v[1] + v[2] + v[3];

    // per-thread partial sums of preceding tile counts (<= 3 reads each)
    int oe = 0, ov = 0;
    for (int t = tid; t < b; t += 256) {
        oe += g_eblk[img * NB + t];
        ov += g_vblk[img * NB + t];
    }

    // warp: inclusive scan of (ce,cv), reduce of (oe,ov)
    int ice = ce, icv = cv;
    #pragma unroll
    for (int off = 1; off < 32; off <<= 1) {
        int a = __shfl_up_sync(0xffffffffu, ice, off);
        int c = __shfl_up_sync(0xffffffffu, icv, off);
        if (lane >= off) { ice += a; icv += c; }
    }
    #pragma unroll
    for (int off = 16; off; off >>= 1) {
        oe += __shfl_down_sync(0xffffffffu, oe, off);
        ov += __shfl_down_sync(0xffffffffu, ov, off);
    }

    __shared__ int wce[8], wcv[8], woe[8], wov[8];
    __shared__ int wbe[8], wbv[8];
    __shared__ int s_offe, s_offv;
    if (lane == 31) { wce[wid] = ice; wcv[wid] = icv; }
    if (lane == 0)  { woe[wid] = oe;  wov[wid] = ov;  }
    __syncthreads();
    if (tid == 0) {
        int offE = 0, offV = 0;
        #pragma unroll
        for (int i = 0; i < 8; i++) { offE += woe[i]; offV += wov[i]; }
        int accE = 0, accV = 0;
        #pragma unroll
        for (int i = 0; i < 8; i++) {
            wbe[i] = accE; accE += wce[i];
            wbv[i] = accV; accV += wcv[i];
        }
        s_offe = offE; s_offv = offV;
        if (b == NB - 1) { g_ecount[img] = offE + accE; g_vcount[img] = offV + accV; }
    }
    __syncthreads();

    int pos_e = s_offe + wbe[wid] + (ice - ce);   // exclusive prefix for this thread
    int pos_v = s_offv + wbv[wid] + (icv - cv);
    int p0 = b * 1024 + tid * 4;

    #pragma unroll
    for (int j = 0; j < 4; j++) {
        if (e[j]) g_epack[(size_t)img * P + pos_e++] = make_int2(p0 + j, __float_as_int(thv[j]));
        if (v[j]) g_vsel [(size_t)img * P + pos_v++] = p0 + j;
    }
}

// ----------------------------------------------------------------------------
// Main sampling kernel: one thread per (img, s). 4 pairs over 6 distinct
// pixels. All random touches are 8B-packed: (pixel,theta) and (inp,tgt).
__global__ void __launch_bounds__(256)
k_sample(const int* __restrict__ ra,
         const int* __restrict__ rd,
         const int* __restrict__ rp) {
    int gid = blockIdx.x * blockDim.x + threadIdx.x;
    double eq = 0.0, uq = 0.0;

    if (gid < NIMG * S) {
        int img = gid / S;
        int s   = gid - img * S;
        const float2* pt_i = g_pt + (size_t)img * P;

        int ec = g_ecount[img];
        int vc = g_vcount[img];

        // anchor = edge_idx[ra % minlen]; ec>0 always when any edge exists
        int anchor; float th;
        if (ec > 0) {
            int2 ap = __ldg(g_epack + (size_t)img * P + (__ldg(ra + gid) % ec));
            anchor = ap.x;
            th     = __int_as_float(ap.y);
        } else {
            anchor = 0;
            th     = g_theta[(size_t)img * P];
        }

        float ct, st;
        sincosf(th, &st, &ct);
        int row_a = anchor / W;
        int col_a = anchor - row_a * W;

        int q[6];
        #pragma unroll
        for (int j = 0; j < 4; j++) {
            int   rdv  = __ldg(rd + ((size_t)img * 4 + j) * S + s);
            float sign = (j < 2) ? -1.0f : 1.0f;
            float d    = ((float)rdv + 2.0f) * sign;
            int cc = col_a + (int)rintf(d * ct);   // jnp.round = half-to-even
            int rr = row_a + (int)rintf(d * st);
            cc = min(max(cc, 0), W - 1);
            rr = min(max(rr, 0), H - 1);
            q[j] = rr * W + cc;
        }

        if (vc > 0) {
            int2 rpv = __ldg((const int2*)(rp + (size_t)img * 2 * S) + s);
            q[4] = __ldg(g_vsel + (size_t)img * P + (rpv.x % vc));
            q[5] = __ldg(g_vsel + (size_t)img * P + (rpv.y % vc));
        } else {
            q[4] = 0; q[5] = 0;    // vidx -> identity, rp % 1 = 0
        }

        // 6 packed gathers (one sector each), issued before any pair math
        float2 pv[6];
        #pragma unroll
        for (int j = 0; j < 6; j++) pv[j] = __ldg(pt_i + q[j]);

        const int PA[4] = {0, 1, 2, 4};
        const int PB[4] = {1, 2, 3, 5};
        const float hi = 1.0f + 0.03f;             // 1 + SIGMA in f32
        const float lo = (float)(1.0 / 1.03);      // double-computed like Python

        #pragma unroll
        for (int k = 0; k < 4; k++) {
            float iA = pv[PA[k]].x, iB = pv[PB[k]].x;
            float tA = pv[PA[k]].y, tB = pv[PB[k]].y;

            float cm = ((tA > MASK_VALUE) && (tB > MASK_VALUE)) ? 1.0f : 0.0f;
            float ratio = (tA + 1e-6f) / (tB + 1e-6f);
            bool  meq = (ratio < hi) && (ratio > lo);

            if (meq) {
                float dd = iA - iB;
                eq += (double)(dd * dd * cm);
            } else {
                float lbl = (ratio >= hi) ? 1.0f : -1.0f;
                uq += (double)(log1pf(expf((iB - iA) * lbl)) * cm);
            }
        }
    }

    // block reduce (doubles) -> single atomicAdd pair per block
    #pragma unroll
    for (int off = 16; off; off >>= 1) {
        eq += __shfl_down_sync(0xffffffffu, eq, off);
        uq += __shfl_down_sync(0xffffffffu, uq, off);
    }
    __shared__ double sh_eq[8];
    __shared__ double sh_uq[8];
    int lane = threadIdx.x & 31, wid = threadIdx.x >> 5;
    if (lane == 0) { sh_eq[wid] = eq; sh_uq[wid] = uq; }
    __syncthreads();
    if (wid == 0) {
        eq = (lane < 8) ? sh_eq[lane] : 0.0;
        uq = (lane < 8) ? sh_uq[lane] : 0.0;
        #pragma unroll
        for (int off = 4; off; off >>= 1) {
            eq += __shfl_down_sync(0xffffffffu, eq, off);
            uq += __shfl_down_sync(0xffffffffu, uq, off);
        }
        if (lane == 0) {
            atomicAdd(&g_acc_eq, eq);
            atomicAdd(&g_acc_uq, uq);
        }
    }
}

// ----------------------------------------------------------------------------
__global__ void k_final(float* __restrict__ out) {
    const double ALPHA = 1.0;
    double denom = 4.0 * (double)S;                       // pairs per image
    double loss  = (ALPHA * g_acc_eq + g_acc_uq) / denom / (double)NIMG;
    out[0] = (float)loss;
}

// ----------------------------------------------------------------------------
extern "C" void kernel_launch(void* const* d_in, const int* in_sizes, int n_in,
                              void* d_out, int out_size) {
    (void)in_sizes; (void)n_in; (void)out_size;

    const float* inputs  = (const float*)d_in[0];
    const float* targets = (const float*)d_in[1];
    const float* images  = (const float*)d_in[2];
    const int*   ra      = (const int*)d_in[3];
    const int*   rd      = (const int*)d_in[4];
    const int*   rp      = (const int*)d_in[5];
    float*       out     = (float*)d_out;

    k_init   <<<1, 32>>>();
    k_sobel  <<<(NIMG * P) / 256, 256>>>(images, inputs, targets);
    k_count  <<<NIMG * NB, 256>>>(targets);
    k_scatter<<<NIMG * NB, 256>>>(targets);
    k_sample <<<(NIMG * S + 255) / 256, 256>>>(ra, rd, rp);
    k_final  <<<1, 1>>>(out);
}

// round 9
// speedup vs baseline: 1.6913x; 1.1943x over previous
#include <cuda_runtime.h>
#include <math.h>

// ---------------------------------------------------------------------------
// GemoLoss — GB300. n=4, h=768, w=1024, S=131072.
// R8: bitmask handoff count->scatter; identity-vsel shortcut (vc==P);
//     4px/thread Sobel; atomic per-image mask totals.
// ---------------------------------------------------------------------------

#define NIMG 4
#define H    768
#define W    1024
#define P    (H * W)          // 786432
#define S    131072
#define NB   (P / 1024)       // 768 tiles of 1024 pixels per image

#define MASK_VALUE (-1e-8f)

// -------------------- device scratch (no allocations allowed) ---------------
__device__ float    g_edge [NIMG * P];
__device__ float    g_theta[NIMG * P];
__device__ float2   g_pt   [NIMG * P];     // packed (inp, tgt) per pixel
__device__ int2     g_epack[NIMG * P];     // packed (pixel, theta_bits), compacted
__device__ int      g_vsel [NIMG * P];     // stable select for valid mask (if needed)
__device__ unsigned g_emaskw[NIMG * NB * 32];  // 1024-bit tile masks
__device__ unsigned g_vmaskw[NIMG * NB * 32];
__device__ unsigned g_emax_bits[NIMG];     // edge max as float bits (edge >= 0)
__device__ int      g_eblk[NIMG * NB];     // per-tile mask counts
__device__ int      g_vblk[NIMG * NB];
__device__ int      g_ecount[NIMG];
__device__ int      g_vcount[NIMG];
__device__ double   g_acc_eq;
__device__ double   g_acc_uq;

// ----------------------------------------------------------------------------
__global__ void k_init() {
    int t = threadIdx.x;
    if (t < NIMG) { g_emax_bits[t] = 0u; g_ecount[t] = 0; g_vcount[t] = 0; }
    if (t == 0) { g_acc_eq = 0.0; g_acc_uq = 0.0; }
}

// ----------------------------------------------------------------------------
// Sobel on channel 0 (cross-correlation). 4 consecutive pixels per thread.
// Border pixels get edge=0, theta=0. Fused per-image max. Packs (inp,tgt).
__global__ void k_sobel(const float* __restrict__ images,
                        const float* __restrict__ inp,
                        const float* __restrict__ tgt) {
    int gid = blockIdx.x * blockDim.x + threadIdx.x;   // < NIMG*P/4
    int img = gid / (P / 4);
    int t   = gid - img * (P / 4);
    int p0  = t * 4;                                   // 4 px, same row (W%4==0)
    int y   = p0 / W;
    int x0  = p0 - y * W;

    // pack (inp,tgt): two float4 stores of interleaved float2s
    {
        float4 iv = __ldg((const float4*)(inp) + gid);
        float4 tv = __ldg((const float4*)(tgt) + gid);
        float4* pt4 = (float4*)g_pt;
        pt4[gid * 2    ] = make_float4(iv.x, tv.x, iv.y, tv.y);
        pt4[gid * 2 + 1] = make_float4(iv.z, tv.z, iv.w, tv.w);
    }

    float e[4]  = {0.f, 0.f, 0.f, 0.f};
    float th[4] = {0.f, 0.f, 0.f, 0.f};
    if (y > 0 && y < H - 1) {
        const float* I = images + (size_t)img * 3 * P;
        float r0[6], r1[6], r2[6];
        float4 a0 = __ldg((const float4*)(I + (y - 1) * W + x0));
        float4 a1 = __ldg((const float4*)(I + (y    ) * W + x0));
        float4 a2 = __ldg((const float4*)(I + (y + 1) * W + x0));
        r0[1]=a0.x; r0[2]=a0.y; r0[3]=a0.z; r0[4]=a0.w;
        r1[1]=a1.x; r1[2]=a1.y; r1[3]=a1.z; r1[4]=a1.w;
        r2[1]=a2.x; r2[2]=a2.y; r2[3]=a2.z; r2[4]=a2.w;
        if (x0 > 0) {
            r0[0] = __ldg(I + (y - 1) * W + x0 - 1);
            r1[0] = __ldg(I + (y    ) * W + x0 - 1);
            r2[0] = __ldg(I + (y + 1) * W + x0 - 1);
        } else { r0[0] = r1[0] = r2[0] = 0.f; }
        if (x0 + 4 < W) {
            r0[5] = __ldg(I + (y - 1) * W + x0 + 4);
            r1[5] = __ldg(I + (y    ) * W + x0 + 4);
            r2[5] = __ldg(I + (y + 1) * W + x0 + 4);
        } else { r0[5] = r1[5] = r2[5] = 0.f; }

        #pragma unroll
        for (int j = 0; j < 4; j++) {
            int x = x0 + j;
            if (x > 0 && x < W - 1) {
                float a  = r0[j], b = r0[j + 1], c = r0[j + 2];
                float d  = r1[j],                f = r1[j + 2];
                float g  = r2[j], hh = r2[j + 1], i = r2[j + 2];
                // kx = [[-1,0,1],[-2,0,2],[-1,0,1]], ky = [[1,2,1],[0,0,0],[-1,-2,-1]]
                float gx = -a;  gx += c;  gx += -2.0f * d;  gx += 2.0f * f;  gx += -g;  gx += i;
                float gy =  a;  gy += 2.0f * b;  gy += c;  gy += -g;  gy += -2.0f * hh; gy += -i;
                e[j]  = sqrtf(gx * gx + gy * gy);
                th[j] = atan2f(gy, gx);
            }
        }
    }
    *(float4*)(g_edge  + (size_t)gid * 4) = make_float4(e[0],  e[1],  e[2],  e[3]);
    *(float4*)(g_theta + (size_t)gid * 4) = make_float4(th[0], th[1], th[2], th[3]);

    // block max -> atomicMax (uint order == float order for non-negative)
    __shared__ float smax[8];
    int lane = threadIdx.x & 31, wid = threadIdx.x >> 5;
    float m = fmaxf(fmaxf(e[0], e[1]), fmaxf(e[2], e[3]));
    #pragma unroll
    for (int off = 16; off; off >>= 1)
        m = fmaxf(m, __shfl_down_sync(0xffffffffu, m, off));
    if (lane == 0) smax[wid] = m;
    __syncthreads();
    if (wid == 0) {
        m = (lane < 8) ? smax[lane] : 0.0f;
        #pragma unroll
        for (int off = 4; off; off >>= 1)
            m = fmaxf(m, __shfl_down_sync(0xffffffffu, m, off));
        if (lane == 0) atomicMax(&g_emax_bits[img], __float_as_uint(m));
    }
}

// ----------------------------------------------------------------------------
// Per-tile counts + 1024-bit masks + atomic per-image totals.
__global__ void k_count(const float* __restrict__ tgt) {
    int img = blockIdx.x / NB;
    int b   = blockIdx.x - img * NB;
    int tid = threadIdx.x;
    int lane = tid & 31, wid = tid >> 5;
    size_t base = (size_t)img * P + (size_t)b * 1024;
    const unsigned full = 0xffffffffu;

    float thresh = 0.1f * __uint_as_float(g_emax_bits[img]);
    float4 ed = *(const float4*)(g_edge + base + tid * 4);
    float4 tg = __ldg((const float4*)(tgt + base) + tid);

    unsigned ne = (unsigned)(ed.x >= thresh)
                | ((unsigned)(ed.y >= thresh) << 1)
                | ((unsigned)(ed.z >= thresh) << 2)
                | ((unsigned)(ed.w >= thresh) << 3);
    unsigned nv = (unsigned)(tg.x > MASK_VALUE)
                | ((unsigned)(tg.y > MASK_VALUE) << 1)
                | ((unsigned)(tg.z > MASK_VALUE) << 2)
                | ((unsigned)(tg.w > MASK_VALUE) << 3);

    // assemble 32-bit words (8 lanes * 4 bits) and store tile masks
    unsigned we = ne << (4 * (lane & 7));
    unsigned wv = nv << (4 * (lane & 7));
    #pragma unroll
    for (int off = 4; off; off >>= 1) {
        we |= __shfl_xor_sync(full, we, off);
        wv |= __shfl_xor_sync(full, wv, off);
    }
    if ((lane & 7) == 0) {
        int widx = (tid >> 3);
        g_emaskw[(size_t)(img * NB + b) * 32 + widx] = we;
        g_vmaskw[(size_t)(img * NB + b) * 32 + widx] = wv;
    }

    int ce = __popc(ne), cv = __popc(nv);
    __shared__ int sce[8], scv[8];
    #pragma unroll
    for (int off = 16; off; off >>= 1) {
        ce += __shfl_down_sync(full, ce, off);
        cv += __shfl_down_sync(full, cv, off);
    }
    if (lane == 0) { sce[wid] = ce; scv[wid] = cv; }
    __syncthreads();
    if (tid == 0) {
        int te = 0, tv = 0;
        #pragma unroll
        for (int i = 0; i < 8; i++) { te += sce[i]; tv += scv[i]; }
        g_eblk[img * NB + b] = te;
        g_vblk[img * NB + b] = tv;
        atomicAdd(&g_ecount[img], te);
        atomicAdd(&g_vcount[img], tv);
    }
}

// ----------------------------------------------------------------------------
// Stable scatter from bitmasks. Tile offset = inline sum of preceding counts.
// If vcount == P (all-valid), vsel is the identity -> skip all v work.
__global__ void k_scatter() {
    int img = blockIdx.x / NB;
    int b   = blockIdx.x - img * NB;
    int tid = threadIdx.x;
    int lane = tid & 31, wid = tid >> 5;
    size_t base = (size_t)img * P + (size_t)b * 1024;
    const unsigned full = 0xffffffffu;

    bool vall = (g_vcount[img] == P);

    unsigned wordE = g_emaskw[(size_t)(img * NB + b) * 32 + (tid >> 3)];
    unsigned ne = (wordE >> (4 * (tid & 7))) & 0xFu;
    unsigned nv = 0;
    if (!vall) {
        unsigned wordV = g_vmaskw[(size_t)(img * NB + b) * 32 + (tid >> 3)];
        nv = (wordV >> (4 * (tid & 7))) & 0xFu;
    }
    float4 th4 = *(const float4*)(g_theta + base + tid * 4);
    float thv[4] = { th4.x, th4.y, th4.z, th4.w };

    int ce = __popc(ne);
    int cv = __popc(nv);

    // per-thread partial sums of preceding tile counts
    int oe = 0, ov = 0;
    for (int t = tid; t < b; t += 256) {
        oe += g_eblk[img * NB + t];
        if (!vall) ov += g_vblk[img * NB + t];
    }

    // warp: inclusive scan of (ce,cv), reduce of (oe,ov)
    int ice = ce, icv = cv;
    #pragma unroll
    for (int off = 1; off < 32; off <<= 1) {
        int a = __shfl_up_sync(full, ice, off);
        int c = __shfl_up_sync(full, icv, off);
        if (lane >= off) { ice += a; icv += c; }
    }
    #pragma unroll
    for (int off = 16; off; off >>= 1) {
        oe += __shfl_down_sync(full, oe, off);
        ov += __shfl_down_sync(full, ov, off);
    }

    __shared__ int wce[8], wcv[8], woe[8], wov[8];
    __shared__ int wbe[8], wbv[8];
    __shared__ int s_offe, s_offv;
    if (lane == 31) { wce[wid] = ice; wcv[wid] = icv; }
    if (lane == 0)  { woe[wid] = oe;  wov[wid] = ov;  }
    __syncthreads();
    if (tid == 0) {
        int offE = 0, offV = 0;
        #pragma unroll
        for (int i = 0; i < 8; i++) { offE += woe[i]; offV += wov[i]; }
        int accE = 0, accV = 0;
        #pragma unroll
        for (int i = 0; i < 8; i++) {
            wbe[i] = accE; accE += wce[i];
            wbv[i] = accV; accV += wcv[i];
        }
        s_offe = offE; s_offv = offV;
    }
    __syncthreads();

    int pos_e = s_offe + wbe[wid] + (ice - ce);
    int p0 = b * 1024 + tid * 4;
    #pragma unroll
    for (int j = 0; j < 4; j++)
        if ((ne >> j) & 1u)
            g_epack[(size_t)img * P + pos_e++] = make_int2(p0 + j, __float_as_int(thv[j]));

    if (!vall) {
        int pos_v = s_offv + wbv[wid] + (icv - cv);
        #pragma unroll
        for (int j = 0; j < 4; j++)
            if ((nv >> j) & 1u)
                g_vsel[(size_t)img * P + pos_v++] = p0 + j;
    }
}

// ----------------------------------------------------------------------------
// Main sampling kernel: one thread per (img, s). 4 pairs over 6 distinct
// pixels. Random touches are 8B-packed: (pixel,theta) and (inp,tgt).
__global__ void __launch_bounds__(256)
k_sample(const int* __restrict__ ra,
         const int* __restrict__ rd,
         const int* __restrict__ rp) {
    int gid = blockIdx.x * blockDim.x + threadIdx.x;
    double eq = 0.0, uq = 0.0;

    if (gid < NIMG * S) {
        int img = gid / S;
        int s   = gid - img * S;
        const float2* pt_i = g_pt + (size_t)img * P;

        int ec = g_ecount[img];
        int vc = g_vcount[img];

        // anchor = edge_idx[ra % minlen]; empty mask -> identity argsort -> 0
        int anchor; float th;
        if (ec > 0) {
            int2 ap = __ldg(g_epack + (size_t)img * P + (__ldg(ra + gid) % ec));
            anchor = ap.x;
            th     = __int_as_float(ap.y);
        } else {
            anchor = 0;
            th     = g_theta[(size_t)img * P];
        }

        float ct, st;
        sincosf(th, &st, &ct);
        int row_a = anchor / W;
        int col_a = anchor - row_a * W;

        int q[6];
        #pragma unroll
        for (int j = 0; j < 4; j++) {
            int   rdv  = __ldg(rd + ((size_t)img * 4 + j) * S + s);
            float sign = (j < 2) ? -1.0f : 1.0f;
            float d    = ((float)rdv + 2.0f) * sign;
            int cc = col_a + (int)rintf(d * ct);   // jnp.round = half-to-even
            int rr = row_a + (int)rintf(d * st);
            cc = min(max(cc, 0), W - 1);
            rr = min(max(rr, 0), H - 1);
            q[j] = rr * W + cc;
        }

        if (vc == P) {                 // all-valid: vsel is identity
            int2 rpv = __ldg((const int2*)(rp + (size_t)img * 2 * S) + s);
            q[4] = rpv.x % vc;
            q[5] = rpv.y % vc;
        } else if (vc > 0) {
            int2 rpv = __ldg((const int2*)(rp + (size_t)img * 2 * S) + s);
            q[4] = __ldg(g_vsel + (size_t)img * P + (rpv.x % vc));
            q[5] = __ldg(g_vsel + (size_t)img * P + (rpv.y % vc));
        } else {
            q[4] = 0; q[5] = 0;        // vidx -> identity, rp % 1 = 0
        }

        // 6 packed gathers (one sector each), issued before any pair math
        float2 pv[6];
        #pragma unroll
        for (int j = 0; j < 6; j++) pv[j] = __ldg(pt_i + q[j]);

        const int PA[4] = {0, 1, 2, 4};
        const int PB[4] = {1, 2, 3, 5};
        const float hi = 1.0f + 0.03f;             // 1 + SIGMA in f32
        const float lo = (float)(1.0 / 1.03);      // double-computed like Python

        #pragma unroll
        for (int k = 0; k < 4; k++) {
            float iA = pv[PA[k]].x, iB = pv[PB[k]].x;
            float tA = pv[PA[k]].y, tB = pv[PB[k]].y;

            float cm = ((tA > MASK_VALUE) && (tB > MASK_VALUE)) ? 1.0f : 0.0f;
            float ratio = (tA + 1e-6f) / (tB + 1e-6f);
            bool  meq = (ratio < hi) && (ratio > lo);

            if (meq) {
                float dd = iA - iB;
                eq += (double)(dd * dd * cm);
            } else {
                float lbl = (ratio >= hi) ? 1.0f : -1.0f;
                uq += (double)(log1pf(expf((iB - iA) * lbl)) * cm);
            }
        }
    }

    // block reduce (doubles) -> single atomicAdd pair per block
    #pragma unroll
    for (int off = 16; off; off >>= 1) {
        eq += __shfl_down_sync(0xffffffffu, eq, off);
        uq += __shfl_down_sync(0xffffffffu, uq, off);
    }
    __shared__ double sh_eq[8];
    __shared__ double sh_uq[8];
    int lane = threadIdx.x & 31, wid = threadIdx.x >> 5;
    if (lane == 0) { sh_eq[wid] = eq; sh_uq[wid] = uq; }
    __syncthreads();
    if (wid == 0) {
        eq = (lane < 8) ? sh_eq[lane] : 0.0;
        uq = (lane < 8) ? sh_uq[lane] : 0.0;
        #pragma unroll
        for (int off = 4; off; off >>= 1) {
            eq += __shfl_down_sync(0xffffffffu, eq, off);
            uq += __shfl_down_sync(0xffffffffu, uq, off);
        }
        if (lane == 0) {
            atomicAdd(&g_acc_eq, eq);
            atomicAdd(&g_acc_uq, uq);
        }
    }
}

// ----------------------------------------------------------------------------
__global__ void k_final(float* __restrict__ out) {
    const double ALPHA = 1.0;
    double denom = 4.0 * (double)S;                       // pairs per image
    double loss  = (ALPHA * g_acc_eq + g_acc_uq) / denom / (double)NIMG;
    out[0] = (float)loss;
}

// ----------------------------------------------------------------------------
extern "C" void kernel_launch(void* const* d_in, const int* in_sizes, int n_in,
                              void* d_out, int out_size) {
    (void)in_sizes; (void)n_in; (void)out_size;

    const float* inputs  = (const float*)d_in[0];
    const float* targets = (const float*)d_in[1];
    const float* images  = (const float*)d_in[2];
    const int*   ra      = (const int*)d_in[3];
    const int*   rd      = (const int*)d_in[4];
    const int*   rp      = (const int*)d_in[5];
    float*       out     = (float*)d_out;

    k_init   <<<1, 32>>>();
    k_sobel  <<<(NIMG * P / 4) / 256, 256>>>(images, inputs, targets);
    k_count  <<<NIMG * NB, 256>>>(targets);
    k_scatter<<<NIMG * NB, 256>>>();
    k_sample <<<(NIMG * S + 255) / 256, 256>>>(ra, rd, rp);
    k_final  <<<1, 1>>>(out);
}

// round 10
// speedup vs baseline: 1.8374x; 1.0863x over previous
#include <cuda_runtime.h>
#include <math.h>

// ---------------------------------------------------------------------------
// GemoLoss — GB300. n=4, h=768, w=1024, S=131072.
// R9: v-mask fused into sobel; smem-staged coalesced scatter; k_init removed
//     (zero-init globals + end-of-pipeline reset in k_final).
// ---------------------------------------------------------------------------

#define NIMG 4
#define H    768
#define W    1024
#define P    (H * W)          // 786432
#define S    131072
#define NB   (P / 1024)       // 768 tiles of 1024 pixels per image

#define MASK_VALUE (-1e-8f)

// ------------- device scratch (zero-initialized at module load) -------------
__device__ float    g_edge [NIMG * P];
__device__ float    g_theta[NIMG * P];
__device__ float2   g_pt   [NIMG * P];        // packed (inp, tgt) per pixel
__device__ int2     g_epack[NIMG * P];        // packed (pixel, theta_bits)
__device__ int      g_vsel [NIMG * P];        // stable select for valid mask
__device__ unsigned g_emaskw[NIMG * NB * 32]; // 1024-bit tile masks
__device__ unsigned g_vmaskw[NIMG * NB * 32];
__device__ unsigned g_emax_bits[NIMG];        // edge max as float bits
__device__ int      g_eblk[NIMG * NB];        // per-tile mask counts
__device__ int      g_vblk[NIMG * NB];
__device__ int      g_ecount[NIMG];
__device__ int      g_vcount[NIMG];
__device__ double   g_acc_eq;
__device__ double   g_acc_uq;

// ----------------------------------------------------------------------------
// Sobel on channel 0 (cross-correlation). One block == one 1024-px tile,
// 4 consecutive pixels per thread. Border pixels get edge=0, theta=0.
// Fused: per-image edge max, (inp,tgt) packing, v-mask bits/counts.
__global__ void k_sobel(const float* __restrict__ images,
                        const float* __restrict__ inp,
                        const float* __restrict__ tgt) {
    int gid = blockIdx.x * blockDim.x + threadIdx.x;   // < NIMG*P/4
    int img = gid / (P / 4);
    int t   = gid - img * (P / 4);
    int p0  = t * 4;                                   // 4 px, same row (W%4==0)
    int y   = p0 / W;
    int x0  = p0 - y * W;
    int tid = threadIdx.x;
    int lane = tid & 31, wid = tid >> 5;
    const unsigned full = 0xffffffffu;

    // pack (inp,tgt) and build v-mask nibble from the same tgt load
    float4 tv = __ldg((const float4*)(tgt) + gid);
    {
        float4 iv = __ldg((const float4*)(inp) + gid);
        float4* pt4 = (float4*)g_pt;
        pt4[gid * 2    ] = make_float4(iv.x, tv.x, iv.y, tv.y);
        pt4[gid * 2 + 1] = make_float4(iv.z, tv.z, iv.w, tv.w);
    }
    unsigned nv = (unsigned)(tv.x > MASK_VALUE)
                | ((unsigned)(tv.y > MASK_VALUE) << 1)
                | ((unsigned)(tv.z > MASK_VALUE) << 2)
                | ((unsigned)(tv.w > MASK_VALUE) << 3);

    float e[4]  = {0.f, 0.f, 0.f, 0.f};
    float th[4] = {0.f, 0.f, 0.f, 0.f};
    if (y > 0 && y < H - 1) {
        const float* I = images + (size_t)img * 3 * P;
        float r0[6], r1[6], r2[6];
        float4 a0 = __ldg((const float4*)(I + (y - 1) * W + x0));
        float4 a1 = __ldg((const float4*)(I + (y    ) * W + x0));
        float4 a2 = __ldg((const float4*)(I + (y + 1) * W + x0));
        r0[1]=a0.x; r0[2]=a0.y; r0[3]=a0.z; r0[4]=a0.w;
        r1[1]=a1.x; r1[2]=a1.y; r1[3]=a1.z; r1[4]=a1.w;
        r2[1]=a2.x; r2[2]=a2.y; r2[3]=a2.z; r2[4]=a2.w;
        if (x0 > 0) {
            r0[0] = __ldg(I + (y - 1) * W + x0 - 1);
            r1[0] = __ldg(I + (y    ) * W + x0 - 1);
            r2[0] = __ldg(I + (y + 1) * W + x0 - 1);
        } else { r0[0] = r1[0] = r2[0] = 0.f; }
        if (x0 + 4 < W) {
            r0[5] = __ldg(I + (y - 1) * W + x0 + 4);
            r1[5] = __ldg(I + (y    ) * W + x0 + 4);
            r2[5] = __ldg(I + (y + 1) * W + x0 + 4);
        } else { r0[5] = r1[5] = r2[5] = 0.f; }

        #pragma unroll
        for (int j = 0; j < 4; j++) {
            int x = x0 + j;
            if (x > 0 && x < W - 1) {
                float a  = r0[j], b = r0[j + 1], c = r0[j + 2];
                float d  = r1[j],                f = r1[j + 2];
                float g  = r2[j], hh = r2[j + 1], i = r2[j + 2];
                // kx = [[-1,0,1],[-2,0,2],[-1,0,1]], ky = [[1,2,1],[0,0,0],[-1,-2,-1]]
                float gx = -a;  gx += c;  gx += -2.0f * d;  gx += 2.0f * f;  gx += -g;  gx += i;
                float gy =  a;  gy += 2.0f * b;  gy += c;  gy += -g;  gy += -2.0f * hh; gy += -i;
                e[j]  = sqrtf(gx * gx + gy * gy);
                th[j] = atan2f(gy, gx);
            }
        }
    }
    *(float4*)(g_edge  + (size_t)gid * 4) = make_float4(e[0],  e[1],  e[2],  e[3]);
    *(float4*)(g_theta + (size_t)gid * 4) = make_float4(th[0], th[1], th[2], th[3]);

    // v-mask word assembly (8 lanes * 4 bits) + tile count
    unsigned wv = nv << (4 * (lane & 7));
    #pragma unroll
    for (int off = 4; off; off >>= 1) wv |= __shfl_xor_sync(full, wv, off);
    if ((lane & 7) == 0)
        g_vmaskw[(size_t)blockIdx.x * 32 + (tid >> 3)] = wv;

    // block reductions: edge max + v count
    __shared__ float smax[8];
    __shared__ int   scv[8];
    float m = fmaxf(fmaxf(e[0], e[1]), fmaxf(e[2], e[3]));
    int cv = __popc(nv);
    #pragma unroll
    for (int off = 16; off; off >>= 1) {
        m  = fmaxf(m, __shfl_down_sync(full, m, off));
        cv += __shfl_down_sync(full, cv, off);
    }
    if (lane == 0) { smax[wid] = m; scv[wid] = cv; }
    __syncthreads();
    if (tid == 0) {
        float mm = smax[0]; int tvc = scv[0];
        #pragma unroll
        for (int i = 1; i < 8; i++) { mm = fmaxf(mm, smax[i]); tvc += scv[i]; }
        g_vblk[blockIdx.x] = tvc;
        atomicAdd(&g_vcount[img], tvc);
        atomicMax(&g_emax_bits[img], __float_as_uint(mm));
    }
}

// ----------------------------------------------------------------------------
// Per-tile e-mask bits + counts (reads g_edge only).
__global__ void k_count() {
    int img = blockIdx.x / NB;
    int tid = threadIdx.x;
    int lane = tid & 31, wid = tid >> 5;
    const unsigned full = 0xffffffffu;

    float thresh = 0.1f * __uint_as_float(g_emax_bits[img]);
    float4 ed = *(const float4*)(g_edge + (size_t)blockIdx.x * 1024 + tid * 4);

    unsigned ne = (unsigned)(ed.x >= thresh)
                | ((unsigned)(ed.y >= thresh) << 1)
                | ((unsigned)(ed.z >= thresh) << 2)
                | ((unsigned)(ed.w >= thresh) << 3);

    unsigned we = ne << (4 * (lane & 7));
    #pragma unroll
    for (int off = 4; off; off >>= 1) we |= __shfl_xor_sync(full, we, off);
    if ((lane & 7) == 0)
        g_emaskw[(size_t)blockIdx.x * 32 + (tid >> 3)] = we;

    int ce = __popc(ne);
    __shared__ int sce[8];
    #pragma unroll
    for (int off = 16; off; off >>= 1) ce += __shfl_down_sync(full, ce, off);
    if (lane == 0) sce[wid] = ce;
    __syncthreads();
    if (tid == 0) {
        int te = 0;
        #pragma unroll
        for (int i = 0; i < 8; i++) te += sce[i];
        g_eblk[blockIdx.x] = te;
        atomicAdd(&g_ecount[img], te);
    }
}

// ----------------------------------------------------------------------------
// Stable scatter from bitmasks, staged through shared memory so all global
// stores are coalesced. Tile offset = inline reduce of preceding tile counts.
// If vcount == P (all-valid), vsel is the identity -> skip all v work.
__global__ void k_scatter() {
    int img = blockIdx.x / NB;
    int b   = blockIdx.x - img * NB;
    int tid = threadIdx.x;
    int lane = tid & 31, wid = tid >> 5;
    const unsigned full = 0xffffffffu;

    bool vall = (g_vcount[img] == P);

    unsigned wordE = g_emaskw[(size_t)blockIdx.x * 32 + (tid >> 3)];
    unsigned ne = (wordE >> (4 * (tid & 7))) & 0xFu;
    unsigned nv = 0;
    if (!vall) {
        unsigned wordV = g_vmaskw[(size_t)blockIdx.x * 32 + (tid >> 3)];
        nv = (wordV >> (4 * (tid & 7))) & 0xFu;
    }
    float4 th4 = *(const float4*)(g_theta + (size_t)blockIdx.x * 1024 + tid * 4);
    float thv[4] = { th4.x, th4.y, th4.z, th4.w };

    int ce = __popc(ne);
    int cv = __popc(nv);

    // per-thread partial sums of preceding tile counts (coalesced)
    int oe = 0, ov = 0;
    for (int t = tid; t < b; t += 256) {
        oe += g_eblk[img * NB + t];
        if (!vall) ov += g_vblk[img * NB + t];
    }

    // warp: inclusive scan of (ce,cv), reduce of (oe,ov)
    int ice = ce, icv = cv;
    #pragma unroll
    for (int off = 1; off < 32; off <<= 1) {
        int a = __shfl_up_sync(full, ice, off);
        int c = __shfl_up_sync(full, icv, off);
        if (lane >= off) { ice += a; icv += c; }
    }
    #pragma unroll
    for (int off = 16; off; off >>= 1) {
        oe += __shfl_down_sync(full, oe, off);
        ov += __shfl_down_sync(full, ov, off);
    }

    __shared__ int wce[8], wcv[8], woe[8], wov[8];
    __shared__ int wbe[8], wbv[8];
    __shared__ int s_offe, s_offv, s_tote, s_totv;
    __shared__ int2 s_e[1024];
    __shared__ int  s_v[1024];
    if (lane == 31) { wce[wid] = ice; wcv[wid] = icv; }
    if (lane == 0)  { woe[wid] = oe;  wov[wid] = ov;  }
    __syncthreads();
    if (tid == 0) {
        int offE = 0, offV = 0;
        #pragma unroll
        for (int i = 0; i < 8; i++) { offE += woe[i]; offV += wov[i]; }
        int accE = 0, accV = 0;
        #pragma unroll
        for (int i = 0; i < 8; i++) {
            wbe[i] = accE; accE += wce[i];
            wbv[i] = accV; accV += wcv[i];
        }
        s_offe = offE; s_offv = offV;
        s_tote = accE; s_totv = accV;
    }
    __syncthreads();

    // compact into shared at stable local ranks
    int le = wbe[wid] + (ice - ce);
    int p0 = b * 1024 + tid * 4;
    #pragma unroll
    for (int j = 0; j < 4; j++)
        if ((ne >> j) & 1u)
            s_e[le++] = make_int2(p0 + j, __float_as_int(thv[j]));
    if (!vall) {
        int lv = wbv[wid] + (icv - cv);
        #pragma unroll
        for (int j = 0; j < 4; j++)
            if ((nv >> j) & 1u)
                s_v[lv++] = p0 + j;
    }
    __syncthreads();

    // coalesced global stores
    size_t imgP = (size_t)img * P;
    int tote = s_tote, offe = s_offe;
    for (int t = tid; t < tote; t += 256)
        g_epack[imgP + offe + t] = s_e[t];
    if (!vall) {
        int totv = s_totv, offv = s_offv;
        for (int t = tid; t < totv; t += 256)
            g_vsel[imgP + offv + t] = s_v[t];
    }
}

// ----------------------------------------------------------------------------
// Main sampling kernel: one thread per (img, s). 4 pairs over 6 distinct
// pixels. Random touches are 8B-packed: (pixel,theta) and (inp,tgt).
__global__ void __launch_bounds__(256)
k_sample(const int* __restrict__ ra,
         const int* __restrict__ rd,
         const int* __restrict__ rp) {
    int gid = blockIdx.x * blockDim.x + threadIdx.x;
    double eq = 0.0, uq = 0.0;

    if (gid < NIMG * S) {
        int img = gid / S;
        int s   = gid - img * S;
        const float2* pt_i = g_pt + (size_t)img * P;

        int ec = g_ecount[img];
        int vc = g_vcount[img];

        // anchor = edge_idx[ra % minlen]; empty mask -> identity argsort -> 0
        int anchor; float th;
        if (ec > 0) {
            int2 ap = __ldg(g_epack + (size_t)img * P + (__ldg(ra + gid) % ec));
            anchor = ap.x;
            th     = __int_as_float(ap.y);
        } else {
            anchor = 0;
            th     = g_theta[(size_t)img * P];
        }

        float ct, st;
        sincosf(th, &st, &ct);
        int row_a = anchor / W;
        int col_a = anchor - row_a * W;

        int q[6];
        #pragma unroll
        for (int j = 0; j < 4; j++) {
            int   rdv  = __ldg(rd + ((size_t)img * 4 + j) * S + s);
            float sign = (j < 2) ? -1.0f : 1.0f;
            float d    = ((float)rdv + 2.0f) * sign;
            int cc = col_a + (int)rintf(d * ct);   // jnp.round = half-to-even
            int rr = row_a + (int)rintf(d * st);
            cc = min(max(cc, 0), W - 1);
            rr = min(max(rr, 0), H - 1);
            q[j] = rr * W + cc;
        }

        if (vc == P) {                 // all-valid: vsel is identity
            int2 rpv = __ldg((const int2*)(rp + (size_t)img * 2 * S) + s);
            q[4] = rpv.x % vc;
            q[5] = rpv.y % vc;
        } else if (vc > 0) {
            int2 rpv = __ldg((const int2*)(rp + (size_t)img * 2 * S) + s);
            q[4] = __ldg(g_vsel + (size_t)img * P + (rpv.x % vc));
            q[5] = __ldg(g_vsel + (size_t)img * P + (rpv.y % vc));
        } else {
            q[4] = 0; q[5] = 0;        // vidx -> identity, rp % 1 = 0
        }

        // 6 packed gathers (one sector each), issued before any pair math
        float2 pv[6];
        #pragma unroll
        for (int j = 0; j < 6; j++) pv[j] = __ldg(pt_i + q[j]);

        const int PA[4] = {0, 1, 2, 4};
        const int PB[4] = {1, 2, 3, 5};
        const float hi = 1.0f + 0.03f;             // 1 + SIGMA in f32
        const float lo = (float)(1.0 / 1.03);      // double-computed like Python

        #pragma unroll
        for (int k = 0; k < 4; k++) {
            float iA = pv[PA[k]].x, iB = pv[PB[k]].x;
            float tA = pv[PA[k]].y, tB = pv[PB[k]].y;

            float cm = ((tA > MASK_VALUE) && (tB > MASK_VALUE)) ? 1.0f : 0.0f;
            float ratio = (tA + 1e-6f) / (tB + 1e-6f);
            bool  meq = (ratio < hi) && (ratio > lo);

            if (meq) {
                float dd = iA - iB;
                eq += (double)(dd * dd * cm);
            } else {
                float lbl = (ratio >= hi) ? 1.0f : -1.0f;
                uq += (double)(log1pf(expf((iB - iA) * lbl)) * cm);
            }
        }
    }

    // block reduce (doubles) -> single atomicAdd pair per block
    #pragma unroll
    for (int off = 16; off; off >>= 1) {
        eq += __shfl_down_sync(0xffffffffu, eq, off);
        uq += __shfl_down_sync(0xffffffffu, uq, off);
    }
    __shared__ double sh_eq[8];
    __shared__ double sh_uq[8];
    int lane = threadIdx.x & 31, wid = threadIdx.x >> 5;
    if (lane == 0) { sh_eq[wid] = eq; sh_uq[wid] = uq; }
    __syncthreads();
    if (wid == 0) {
        eq = (lane < 8) ? sh_eq[lane] : 0.0;
        uq = (lane < 8) ? sh_uq[lane] : 0.0;
        #pragma unroll
        for (int off = 4; off; off >>= 1) {
            eq += __shfl_down_sync(0xffffffffu, eq, off);
            uq += __shfl_down_sync(0xffffffffu, uq, off);
        }
        if (lane == 0) {
            atomicAdd(&g_acc_eq, eq);
            atomicAdd(&g_acc_uq, uq);
        }
    }
}

// ----------------------------------------------------------------------------
// Final: compute loss, then reset all global accumulators/counters so the
// next invocation (graph replay) starts from the same zero state.
__global__ void k_final(float* __restrict__ out) {
    int t = threadIdx.x;
    if (t == 0) {
        const double ALPHA = 1.0;
        double denom = 4.0 * (double)S;                   // pairs per image
        double loss  = (ALPHA * g_acc_eq + g_acc_uq) / denom / (double)NIMG;
        out[0] = (float)loss;
        g_acc_eq = 0.0;
        g_acc_uq = 0.0;
    }
    if (t < NIMG) {
        g_emax_bits[t] = 0u;
        g_ecount[t] = 0;
        g_vcount[t] = 0;
    }
}

// ----------------------------------------------------------------------------
extern "C" void kernel_launch(void* const* d_in, const int* in_sizes, int n_in,
                              void* d_out, int out_size) {
    (void)in_sizes; (void)n_in; (void)out_size;

    const float* inputs  = (const float*)d_in[0];
    const float* targets = (const float*)d_in[1];
    const float* images  = (const float*)d_in[2];
    const int*   ra      = (const int*)d_in[3];
    const int*   rd      = (const int*)d_in[4];
    const int*   rp      = (const int*)d_in[5];
    float*       out     = (float*)d_out;

    k_sobel  <<<NIMG * NB, 256>>>(images, inputs, targets);
    k_count  <<<NIMG * NB, 256>>>();
    k_scatter<<<NIMG * NB, 256>>>();
    k_sample <<<(NIMG * S + 255) / 256, 256>>>(ra, rd, rp);
    k_final  <<<1, 32>>>(out);
}

// round 12
// speedup vs baseline: 2.2258x; 1.2114x over previous
#include <cuda_runtime.h>
#include <math.h>

// ---------------------------------------------------------------------------
// GemoLoss — GB300. n=4, h=768, w=1024, S=131072.
// R10: k_sample with 4 samples/thread (ILP batching of both random-gather
//      phases, int4-vectorized sequential inputs, float intra-thread acc).
// ---------------------------------------------------------------------------

#define NIMG 4
#define H    768
#define W    1024
#define P    (H * W)          // 786432
#define S    131072
#define NB   (P / 1024)       // 768 tiles of 1024 pixels per image

#define MASK_VALUE (-1e-8f)

// ------------- device scratch (zero-initialized at module load) -------------
__device__ float    g_edge [NIMG * P];
__device__ float    g_theta[NIMG * P];
__device__ float2   g_pt   [NIMG * P];        // packed (inp, tgt) per pixel
__device__ int2     g_epack[NIMG * P];        // packed (pixel, theta_bits)
__device__ int      g_vsel [NIMG * P];        // stable select for valid mask
__device__ unsigned g_emaskw[NIMG * NB * 32]; // 1024-bit tile masks
__device__ unsigned g_vmaskw[NIMG * NB * 32];
__device__ unsigned g_emax_bits[NIMG];        // edge max as float bits
__device__ int      g_eblk[NIMG * NB];        // per-tile mask counts
__device__ int      g_vblk[NIMG * NB];
__device__ int      g_ecount[NIMG];
__device__ int      g_vcount[NIMG];
__device__ double   g_acc_eq;
__device__ double   g_acc_uq;

// ----------------------------------------------------------------------------
// Sobel on channel 0 (cross-correlation). One block == one 1024-px tile,
// 4 consecutive pixels per thread. Border pixels get edge=0, theta=0.
// Fused: per-image edge max, (inp,tgt) packing, v-mask bits/counts.
__global__ void k_sobel(const float* __restrict__ images,
                        const float* __restrict__ inp,
                        const float* __restrict__ tgt) {
    int gid = blockIdx.x * blockDim.x + threadIdx.x;   // < NIMG*P/4
    int img = gid / (P / 4);
    int t   = gid - img * (P / 4);
    int p0  = t * 4;                                   // 4 px, same row (W%4==0)
    int y   = p0 / W;
    int x0  = p0 - y * W;
    int tid = threadIdx.x;
    int lane = tid & 31, wid = tid >> 5;
    const unsigned full = 0xffffffffu;

    // pack (inp,tgt) and build v-mask nibble from the same tgt load
    float4 tv = __ldg((const float4*)(tgt) + gid);
    {
        float4 iv = __ldg((const float4*)(inp) + gid);
        float4* pt4 = (float4*)g_pt;
        pt4[gid * 2    ] = make_float4(iv.x, tv.x, iv.y, tv.y);
        pt4[gid * 2 + 1] = make_float4(iv.z, tv.z, iv.w, tv.w);
    }
    unsigned nv = (unsigned)(tv.x > MASK_VALUE)
                | ((unsigned)(tv.y > MASK_VALUE) << 1)
                | ((unsigned)(tv.z > MASK_VALUE) << 2)
                | ((unsigned)(tv.w > MASK_VALUE) << 3);

    float e[4]  = {0.f, 0.f, 0.f, 0.f};
    float th[4] = {0.f, 0.f, 0.f, 0.f};
    if (y > 0 && y < H - 1) {
        const float* I = images + (size_t)img * 3 * P;
        float r0[6], r1[6], r2[6];
        float4 a0 = __ldg((const float4*)(I + (y - 1) * W + x0));
        float4 a1 = __ldg((const float4*)(I + (y    ) * W + x0));
        float4 a2 = __ldg((const float4*)(I + (y + 1) * W + x0));
        r0[1]=a0.x; r0[2]=a0.y; r0[3]=a0.z; r0[4]=a0.w;
        r1[1]=a1.x; r1[2]=a1.y; r1[3]=a1.z; r1[4]=a1.w;
        r2[1]=a2.x; r2[2]=a2.y; r2[3]=a2.z; r2[4]=a2.w;
        if (x0 > 0) {
            r0[0] = __ldg(I + (y - 1) * W + x0 - 1);
            r1[0] = __ldg(I + (y    ) * W + x0 - 1);
            r2[0] = __ldg(I + (y + 1) * W + x0 - 1);
        } else { r0[0] = r1[0] = r2[0] = 0.f; }
        if (x0 + 4 < W) {
            r0[5] = __ldg(I + (y - 1) * W + x0 + 4);
            r1[5] = __ldg(I + (y    ) * W + x0 + 4);
            r2[5] = __ldg(I + (y + 1) * W + x0 + 4);
        } else { r0[5] = r1[5] = r2[5] = 0.f; }

        #pragma unroll
        for (int j = 0; j < 4; j++) {
            int x = x0 + j;
            if (x > 0 && x < W - 1) {
                float a  = r0[j], b = r0[j + 1], c = r0[j + 2];
                float d  = r1[j],                f = r1[j + 2];
                float g  = r2[j], hh = r2[j + 1], i = r2[j + 2];
                // kx = [[-1,0,1],[-2,0,2],[-1,0,1]], ky = [[1,2,1],[0,0,0],[-1,-2,-1]]
                float gx = -a;  gx += c;  gx += -2.0f * d;  gx += 2.0f * f;  gx += -g;  gx += i;
                float gy =  a;  gy += 2.0f * b;  gy += c;  gy += -g;  gy += -2.0f * hh; gy += -i;
                e[j]  = sqrtf(gx * gx + gy * gy);
                th[j] = atan2f(gy, gx);
            }
        }
    }
    *(float4*)(g_edge  + (size_t)gid * 4) = make_float4(e[0],  e[1],  e[2],  e[3]);
    *(float4*)(g_theta + (size_t)gid * 4) = make_float4(th[0], th[1], th[2], th[3]);

    // v-mask word assembly (8 lanes * 4 bits) + tile count
    unsigned wv = nv << (4 * (lane & 7));
    #pragma unroll
    for (int off = 4; off; off >>= 1) wv |= __shfl_xor_sync(full, wv, off);
    if ((lane & 7) == 0)
        g_vmaskw[(size_t)blockIdx.x * 32 + (tid >> 3)] = wv;

    // block reductions: edge max + v count
    __shared__ float smax[8];
    __shared__ int   scv[8];
    float m = fmaxf(fmaxf(e[0], e[1]), fmaxf(e[2], e[3]));
    int cv = __popc(nv);
    #pragma unroll
    for (int off = 16; off; off >>= 1) {
        m  = fmaxf(m, __shfl_down_sync(full, m, off));
        cv += __shfl_down_sync(full, cv, off);
    }
    if (lane == 0) { smax[wid] = m; scv[wid] = cv; }
    __syncthreads();
    if (tid == 0) {
        float mm = smax[0]; int tvc = scv[0];
        #pragma unroll
        for (int i = 1; i < 8; i++) { mm = fmaxf(mm, smax[i]); tvc += scv[i]; }
        g_vblk[blockIdx.x] = tvc;
        atomicAdd(&g_vcount[img], tvc);
        atomicMax(&g_emax_bits[img], __float_as_uint(mm));
    }
}

// ----------------------------------------------------------------------------
// Per-tile e-mask bits + counts (reads g_edge only).
__global__ void k_count() {
    int img = blockIdx.x / NB;
    int tid = threadIdx.x;
    int lane = tid & 31, wid = tid >> 5;
    const unsigned full = 0xffffffffu;

    float thresh = 0.1f * __uint_as_float(g_emax_bits[img]);
    float4 ed = *(const float4*)(g_edge + (size_t)blockIdx.x * 1024 + tid * 4);

    unsigned ne = (unsigned)(ed.x >= thresh)
                | ((unsigned)(ed.y >= thresh) << 1)
                | ((unsigned)(ed.z >= thresh) << 2)
                | ((unsigned)(ed.w >= thresh) << 3);

    unsigned we = ne << (4 * (lane & 7));
    #pragma unroll
    for (int off = 4; off; off >>= 1) we |= __shfl_xor_sync(full, we, off);
    if ((lane & 7) == 0)
        g_emaskw[(size_t)blockIdx.x * 32 + (tid >> 3)] = we;

    int ce = __popc(ne);
    __shared__ int sce[8];
    #pragma unroll
    for (int off = 16; off; off >>= 1) ce += __shfl_down_sync(full, ce, off);
    if (lane == 0) sce[wid] = ce;
    __syncthreads();
    if (tid == 0) {
        int te = 0;
        #pragma unroll
        for (int i = 0; i < 8; i++) te += sce[i];
        g_eblk[blockIdx.x] = te;
        atomicAdd(&g_ecount[img], te);
    }
}

// ----------------------------------------------------------------------------
// Stable scatter from bitmasks, staged through shared memory so all global
// stores are coalesced. Tile offset = inline reduce of preceding tile counts.
// If vcount == P (all-valid), vsel is the identity -> skip all v work.
__global__ void k_scatter() {
    int img = blockIdx.x / NB;
    int b   = blockIdx.x - img * NB;
    int tid = threadIdx.x;
    int lane = tid & 31, wid = tid >> 5;
    const unsigned full = 0xffffffffu;

    bool vall = (g_vcount[img] == P);

    unsigned wordE = g_emaskw[(size_t)blockIdx.x * 32 + (tid >> 3)];
    unsigned ne = (wordE >> (4 * (tid & 7))) & 0xFu;
    unsigned nv = 0;
    if (!vall) {
        unsigned wordV = g_vmaskw[(size_t)blockIdx.x * 32 + (tid >> 3)];
        nv = (wordV >> (4 * (tid & 7))) & 0xFu;
    }
    float4 th4 = *(const float4*)(g_theta + (size_t)blockIdx.x * 1024 + tid * 4);
    float thv[4] = { th4.x, th4.y, th4.z, th4.w };

    int ce = __popc(ne);
    int cv = __popc(nv);

    // per-thread partial sums of preceding tile counts (coalesced)
    int oe = 0, ov = 0;
    for (int t = tid; t < b; t += 256) {
        oe += g_eblk[img * NB + t];
        if (!vall) ov += g_vblk[img * NB + t];
    }

    // warp: inclusive scan of (ce,cv), reduce of (oe,ov)
    int ice = ce, icv = cv;
    #pragma unroll
    for (int off = 1; off < 32; off <<= 1) {
        int a = __shfl_up_sync(full, ice, off);
        int c = __shfl_up_sync(full, icv, off);
        if (lane >= off) { ice += a; icv += c; }
    }
    #pragma unroll
    for (int off = 16; off; off >>= 1) {
        oe += __shfl_down_sync(full, oe, off);
        ov += __shfl_down_sync(full, ov, off);
    }

    __shared__ int wce[8], wcv[8], woe[8], wov[8];
    __shared__ int wbe[8], wbv[8];
    __shared__ int s_offe, s_offv, s_tote, s_totv;
    __shared__ int2 s_e[1024];
    __shared__ int  s_v[1024];
    if (lane == 31) { wce[wid] = ice; wcv[wid] = icv; }
    if (lane == 0)  { woe[wid] = oe;  wov[wid] = ov;  }
    __syncthreads();
    if (tid == 0) {
        int offE = 0, offV = 0;
        #pragma unroll
        for (int i = 0; i < 8; i++) { offE += woe[i]; offV += wov[i]; }
        int accE = 0, accV = 0;
        #pragma unroll
        for (int i = 0; i < 8; i++) {
            wbe[i] = accE; accE += wce[i];
            wbv[i] = accV; accV += wcv[i];
        }
        s_offe = offE; s_offv = offV;
        s_tote = accE; s_totv = accV;
    }
    __syncthreads();

    // compact into shared at stable local ranks
    int le = wbe[wid] + (ice - ce);
    int p0 = b * 1024 + tid * 4;
    #pragma unroll
    for (int j = 0; j < 4; j++)
        if ((ne >> j) & 1u)
            s_e[le++] = make_int2(p0 + j, __float_as_int(thv[j]));
    if (!vall) {
        int lv = wbv[wid] + (icv - cv);
        #pragma unroll
        for (int j = 0; j < 4; j++)
            if ((nv >> j) & 1u)
                s_v[lv++] = p0 + j;
    }
    __syncthreads();

    // coalesced global stores
    size_t imgP = (size_t)img * P;
    int tote = s_tote, offe = s_offe;
    for (int t = tid; t < tote; t += 256)
        g_epack[imgP + offe + t] = s_e[t];
    if (!vall) {
        int totv = s_totv, offv = s_offv;
        for (int t = tid; t < totv; t += 256)
            g_vsel[imgP + offv + t] = s_v[t];
    }
}

// ----------------------------------------------------------------------------
// Main sampling kernel: ONE THREAD = FOUR consecutive samples. Both random
// phases (epack anchors, pt gathers) are batched 4-wide for MLP; all
// sequential inputs are int4 loads. Intra-thread accumulation in float
// (16 pair terms), promoted to double at the reduce.
#define IPT 4
__global__ void __launch_bounds__(128)
k_sample(const int* __restrict__ ra,
         const int* __restrict__ rd,
         const int* __restrict__ rp) {
    int t = blockIdx.x * blockDim.x + threadIdx.x;   // < NIMG*S/IPT
    float eqf = 0.0f, uqf = 0.0f;

    {
        int img = t / (S / IPT);
        int g   = t - img * (S / IPT);               // sample group in image
        size_t imgP = (size_t)img * P;
        const float2* pt_i = g_pt + imgP;

        int ec = g_ecount[img];
        int vc = g_vcount[img];

        // ---- phase 0: vectorized sequential inputs ----
        int4 rav  = __ldg((const int4*)ra + img * (S / IPT) + g);
        int4 rdv[4];
        #pragma unroll
        for (int j = 0; j < 4; j++)
            rdv[j] = __ldg((const int4*)rd + (img * 4 + j) * (S / IPT) + g);
        int4 rpa = __ldg((const int4*)rp + img * (S / 2) + 2 * g);      // s0,s1
        int4 rpb = __ldg((const int4*)rp + img * (S / 2) + 2 * g + 1);  // s2,s3
        int rav_i[IPT] = { rav.x, rav.y, rav.z, rav.w };
        int rpA[IPT]   = { rpa.x, rpa.z, rpb.x, rpb.z };
        int rpB[IPT]   = { rpa.y, rpa.w, rpb.y, rpb.w };

        // ---- phase 1: 4 independent anchor gathers ----
        int2 ap[IPT];
        if (ec > 0) {
            #pragma unroll
            for (int i = 0; i < IPT; i++)
                ap[i] = __ldg(g_epack + imgP + (rav_i[i] % ec));
        } else {
            int2 z = make_int2(0, __float_as_int(g_theta[imgP]));
            #pragma unroll
            for (int i = 0; i < IPT; i++) ap[i] = z;
        }

        // ---- phase 2: trig + index computation (all samples) ----
        int q[IPT][6];
        #pragma unroll
        for (int i = 0; i < IPT; i++) {
            float th = __int_as_float(ap[i].y);
            float ct, st;
            sincosf(th, &st, &ct);
            int row_a = ap[i].x / W;
            int col_a = ap[i].x - row_a * W;
            int rdj[4] = { (&rdv[0].x)[i], (&rdv[1].x)[i], (&rdv[2].x)[i], (&rdv[3].x)[i] };
            #pragma unroll
            for (int j = 0; j < 4; j++) {
                float sign = (j < 2) ? -1.0f : 1.0f;
                float d    = ((float)rdj[j] + 2.0f) * sign;
                int cc = col_a + (int)rintf(d * ct);   // jnp.round = half-to-even
                int rr = row_a + (int)rintf(d * st);
                cc = min(max(cc, 0), W - 1);
                rr = min(max(rr, 0), H - 1);
                q[i][j] = rr * W + cc;
            }
        }
        if (vc == P) {                 // all-valid: vsel is identity
            #pragma unroll
            for (int i = 0; i < IPT; i++) {
                q[i][4] = rpA[i] % vc;
                q[i][5] = rpB[i] % vc;
            }
        } else if (vc > 0) {
            #pragma unroll
            for (int i = 0; i < IPT; i++) {
                q[i][4] = __ldg(g_vsel + imgP + (rpA[i] % vc));
                q[i][5] = __ldg(g_vsel + imgP + (rpB[i] % vc));
            }
        } else {
            #pragma unroll
            for (int i = 0; i < IPT; i++) { q[i][4] = 0; q[i][5] = 0; }
        }

        // ---- phase 3: 24 independent packed gathers ----
        float2 pv[IPT][6];
        #pragma unroll
        for (int i = 0; i < IPT; i++)
            #pragma unroll
            for (int j = 0; j < 6; j++)
                pv[i][j] = __ldg(pt_i + q[i][j]);

        // ---- phase 4: pair math ----
        const int PA[4] = {0, 1, 2, 4};
        const int PB[4] = {1, 2, 3, 5};
        const float hi = 1.0f + 0.03f;             // 1 + SIGMA in f32
        const float lo = (float)(1.0 / 1.03);      // double-computed like Python

        #pragma unroll
        for (int i = 0; i < IPT; i++) {
            #pragma unroll
            for (int k = 0; k < 4; k++) {
                float iA = pv[i][PA[k]].x, iB = pv[i][PB[k]].x;
                float tA = pv[i][PA[k]].y, tB = pv[i][PB[k]].y;

                float cm = ((tA > MASK_VALUE) && (tB > MASK_VALUE)) ? 1.0f : 0.0f;
                float ratio = (tA + 1e-6f) / (tB + 1e-6f);
                bool  meq = (ratio < hi) && (ratio > lo);

                if (meq) {
                    float dd = iA - iB;
                    eqf += dd * dd * cm;
                } else {
                    float lbl = (ratio >= hi) ? 1.0f : -1.0f;
                    uqf += log1pf(expf((iB - iA) * lbl)) * cm;
                }
            }
        }
    }

    // block reduce (promote to double) -> single atomicAdd pair per block
    double eq = (double)eqf, uq = (double)uqf;
    #pragma unroll
    for (int off = 16; off; off >>= 1) {
        eq += __shfl_down_sync(0xffffffffu, eq, off);
        uq += __shfl_down_sync(0xffffffffu, uq, off);
    }
    __shared__ double sh_eq[4];
    __shared__ double sh_uq[4];
    int lane = threadIdx.x & 31, wid = threadIdx.x >> 5;
    if (lane == 0) { sh_eq[wid] = eq; sh_uq[wid] = uq; }
    __syncthreads();
    if (wid == 0 && lane == 0) {
        eq = sh_eq[0] + sh_eq[1] + sh_eq[2] + sh_eq[3];
        uq = sh_uq[0] + sh_uq[1] + sh_uq[2] + sh_uq[3];
        atomicAdd(&g_acc_eq, eq);
        atomicAdd(&g_acc_uq, uq);
    }
}

// ----------------------------------------------------------------------------
// Final: compute loss, then reset all global accumulators/counters so the
// next invocation (graph replay) starts from the same zero state.
__global__ void k_final(float* __restrict__ out) {
    int t = threadIdx.x;
    if (t == 0) {
        const double ALPHA = 1.0;
        double denom = 4.0 * (double)S;                   // pairs per image
        double loss  = (ALPHA * g_acc_eq + g_acc_uq) / denom / (double)NIMG;
        out[0] = (float)loss;
        g_acc_eq = 0.0;
        g_acc_uq = 0.0;
    }
    if (t < NIMG) {
        g_emax_bits[t] = 0u;
        g_ecount[t] = 0;
        g_vcount[t] = 0;
    }
}

// ----------------------------------------------------------------------------
extern "C" void kernel_launch(void* const* d_in, const int* in_sizes, int n_in,
                              void* d_out, int out_size) {
    (void)in_sizes; (void)n_in; (void)out_size;

    const float* inputs  = (const float*)d_in[0];
    const float* targets = (const float*)d_in[1];
    const float* images  = (const float*)d_in[2];
    const int*   ra      = (const int*)d_in[3];
    const int*   rd      = (const int*)d_in[4];
    const int*   rp      = (const int*)d_in[5];
    float*       out     = (float*)d_out;

    k_sobel  <<<NIMG * NB, 256>>>(images, inputs, targets);
    k_count  <<<NIMG * NB, 256>>>();
    k_scatter<<<NIMG * NB, 256>>>();
    k_sample <<<(NIMG * S / IPT) / 128, 128>>>(ra, rd, rp);
    k_final  <<<1, 32>>>(out);
}